// round 8
// baseline (speedup 1.0000x reference)
#include <cuda_runtime.h>
#include <math.h>
#include <stdint.h>

#define NN 50000
#define EE 800000
#define DD 256
#define HID 1024
#define STEPS 6

// ---------------- scratch (device globals; no runtime allocation) -------------
__device__ int   g_deg[NN];
__device__ int   g_tmp[NN];
__device__ int   g_rowptr[NN + 1];
__device__ int   g_srcs[EE];
__device__ float g_eas[EE];           // edge_attr, CSR-sorted
__device__ int   g_lts[EE];           // link_type, CSR-sorted
__device__ float g_xd[NN * 8];        // x @ Watt[0:32]
__device__ float g_xs[NN * 8];        // x @ Watt[32:64]
__device__ float g_xlin[NN * 32];     // x @ Wlin[0:32]
__device__ float g_m[NN * DD];        // running node state
__device__ float g_f[NN * DD];        // FFN out scratch
__device__ float g_hidden[NN * HID];  // FFN hidden
// rank-1 edge-constant tables (leaky is positively homogeneous in scalar ea)
__device__ float g_cvp[32], g_cvn[32];   // message vec for a>0 / a<0
__device__ float g_avp[8],  g_avn[8];    // attention vec for a>0 / a<0
__device__ float g_ete[3 * 8];           // link-type attention table
// precomputed tf32 hi/lo splits of the FFN weights (all 6 steps)
__device__ float g_w1h[STEPS * DD * HID];
__device__ float g_w1l[STEPS * DD * HID];
__device__ float g_w2h[STEPS * HID * DD];
__device__ float g_w2l[STEPS * HID * DD];

// ---------------- tf32 split helpers -------------------------------------------
__device__ __forceinline__ void tf32_split(float x, float& hi, float& lo) {
    uint32_t h;
    asm("cvt.rna.tf32.f32 %0, %1;" : "=r"(h) : "f"(x));
    float hf = __uint_as_float(h);
    float r = x - hf;
    uint32_t l;
    asm("cvt.rna.tf32.f32 %0, %1;" : "=r"(l) : "f"(r));
    hi = hf; lo = __uint_as_float(l);
}

// ---------------- preprocessing ------------------------------------------------
__global__ void zero_kernel() {
    int i = blockIdx.x * blockDim.x + threadIdx.x;
    if (i < NN) { g_deg[i] = 0; g_tmp[i] = 0; }
}

__global__ void hist_kernel(const int* __restrict__ dst) {
    int e = blockIdx.x * blockDim.x + threadIdx.x;
    if (e < EE) atomicAdd(&g_deg[dst[e]], 1);
}

__global__ void scan_kernel() {
    __shared__ int ws[32];
    __shared__ int carry_s;
    int tid = threadIdx.x, lane = tid & 31, wid = tid >> 5;
    if (tid == 0) carry_s = 0;
    __syncthreads();
    for (int base = 0; base < NN; base += 1024) {
        int i = base + tid;
        int v = (i < NN) ? g_deg[i] : 0;
        int x = v;
        #pragma unroll
        for (int o = 1; o < 32; o <<= 1) {
            int y = __shfl_up_sync(0xffffffffu, x, o);
            if (lane >= o) x += y;
        }
        if (lane == 31) ws[wid] = x;
        __syncthreads();
        if (tid < 32) {
            int w = ws[tid];
            #pragma unroll
            for (int o = 1; o < 32; o <<= 1) {
                int y = __shfl_up_sync(0xffffffffu, w, o);
                if (tid >= o) w += y;
            }
            ws[tid] = w;
        }
        __syncthreads();
        int incl = x + (wid > 0 ? ws[wid - 1] : 0);
        int carry = carry_s;
        if (i < NN) g_rowptr[i] = carry + incl - v;  // exclusive
        __syncthreads();
        if (tid == 1023) carry_s = carry + incl;
        __syncthreads();
    }
    if (tid == 0) g_rowptr[NN] = carry_s;
}

// CSR scatter: also gather per-edge scalars (edge_attr, link_type) directly
__global__ void scatter_kernel(const int* __restrict__ src, const int* __restrict__ dst,
                               const float* __restrict__ ea, const int* __restrict__ ltype) {
    int e = blockIdx.x * blockDim.x + threadIdx.x;
    if (e >= EE) return;
    int d = dst[e];
    int r = atomicAdd(&g_tmp[d], 1);
    int pos = g_rowptr[d] + r;
    g_srcs[pos] = src[e];
    g_eas[pos]  = ea[e];
    g_lts[pos]  = ltype[e];
}

// rank-1 edge-constant tables. leaky(a*w) = a*leaky(w) for a>0,
// = a*leakyneg(w) for a<0, where leakyneg(w) = (w>0 ? 0.2w : w).
__global__ void prep_tables_kernel(const float* __restrict__ Wea,
                                   const float* __restrict__ Watt,
                                   const float* __restrict__ Et,
                                   const float* __restrict__ Wlin) {
    int lane = threadIdx.x;  // one warp
    float cp = 0.f, cn = 0.f;
    #pragma unroll
    for (int j = 0; j < 50; j++) {
        float w = Wea[j];
        float lp = w > 0.f ? w : 0.2f * w;        // leaky(w)
        float ln_ = w > 0.f ? 0.2f * w : w;       // leakyneg(w)
        float wl = Wlin[(32 + j) * 32 + lane];
        cp = fmaf(lp, wl, cp);
        cn = fmaf(ln_, wl, cn);
    }
    g_cvp[lane] = cp; g_cvn[lane] = cn;
    if (lane < 8) {
        float ap = 0.f, an = 0.f;
        #pragma unroll
        for (int j = 0; j < 50; j++) {
            float w = Wea[j];
            float lp = w > 0.f ? w : 0.2f * w;
            float ln_ = w > 0.f ? 0.2f * w : w;
            float wa = Watt[(74 + j) * 8 + lane];
            ap = fmaf(lp, wa, ap);
            an = fmaf(ln_, wa, an);
        }
        g_avp[lane] = ap; g_avn[lane] = an;
        #pragma unroll
        for (int lt = 0; lt < 3; lt++) {
            float s = 0.f;
            #pragma unroll
            for (int j = 0; j < 10; j++) {
                float t = Et[lt * 10 + j];
                t = t > 0.f ? t : 0.2f * t;
                s = fmaf(t, Watt[(64 + j) * 8 + lane], s);
            }
            g_ete[lt * 8 + lane] = s;
        }
    }
}

// split both FFN weight tensors (all steps) into tf32 hi/lo once per launch
__global__ void split_w_kernel(const float* __restrict__ w1, const float* __restrict__ w2) {
    int i = blockIdx.x * blockDim.x + threadIdx.x;
    const int n1 = STEPS * DD * HID;
    if (i < n1) {
        float hi, lo;
        tf32_split(w1[i], hi, lo);
        g_w1h[i] = hi; g_w1l[i] = lo;
        tf32_split(w2[i], hi, lo);
        g_w2h[i] = hi; g_w2l[i] = lo;
    }
}

// -------------- per-step: HeteroLinear + fused projections ---------------------
__global__ void hetero_kernel(const int* __restrict__ ntype,
                              const float* __restrict__ Wh, const float* __restrict__ bh,
                              const float* __restrict__ Watt, const float* __restrict__ Wlin) {
    int warp = (blockIdx.x * blockDim.x + threadIdx.x) >> 5;
    int lane = threadIdx.x & 31;
    int n0 = warp * 4;
    if (n0 >= NN) return;
    float acc0[4] = {0.f, 0.f, 0.f, 0.f};
    float acc1[4] = {0.f, 0.f, 0.f, 0.f};
    for (int j = 0; j < DD; j += 4) {
        float mv[4][4];
        #pragma unroll
        for (int q = 0; q < 4; q++) {
            int n = n0 + q;
            float4 t = (n < NN) ? *(const float4*)(g_m + (size_t)n * DD + j)
                                : make_float4(0.f, 0.f, 0.f, 0.f);
            mv[q][0] = t.x; mv[q][1] = t.y; mv[q][2] = t.z; mv[q][3] = t.w;
        }
        #pragma unroll
        for (int jj = 0; jj < 4; jj++) {
            float w0 = Wh[(j + jj) * 32 + lane];
            float w1 = Wh[DD * 32 + (j + jj) * 32 + lane];
            #pragma unroll
            for (int q = 0; q < 4; q++) {
                acc0[q] = fmaf(mv[q][jj], w0, acc0[q]);
                acc1[q] = fmaf(mv[q][jj], w1, acc1[q]);
            }
        }
    }
    for (int q = 0; q < 4; q++) {
        int n = n0 + q;
        if (n >= NN) break;
        int t = ntype[n];
        float xv = (t == 0 ? acc0[q] : acc1[q]) + bh[t * 32 + lane];
        #pragma unroll
        for (int h = 0; h < 8; h++) {
            float pd = xv * Watt[lane * 8 + h];
            float ps = xv * Watt[(32 + lane) * 8 + h];
            #pragma unroll
            for (int o = 16; o > 0; o >>= 1) {
                pd += __shfl_xor_sync(0xffffffffu, pd, o);
                ps += __shfl_xor_sync(0xffffffffu, ps, o);
            }
            if (lane == 0) { g_xd[n * 8 + h] = pd; g_xs[n * 8 + h] = ps; }
        }
        float xl = 0.f;
        #pragma unroll
        for (int c = 0; c < 32; c++) {
            float xb = __shfl_sync(0xffffffffu, xv, c);
            xl = fmaf(xb, Wlin[c * 32 + lane], xl);
        }
        g_xlin[n * 32 + lane] = xl;
    }
}

// -------------- per-step: attention + aggregation + fused LayerNorm-1 ----------
// logits recomputed from rank-1 tables in both passes (no edge scratch):
//   logit = leaky(xd[h] + xs[src,h] + Ete[lt,h] + a * av±[h])
//   msg   = xlin[src,c] + a * cv±[c]
// epilogue: the warp holds the full 256-wide hconv row; add residual (g_m row),
// LayerNorm in-warp (identical reduction to ln_kernel), write g_m directly.
__global__ void att_ln_kernel(const float* __restrict__ gg, const float* __restrict__ bb) {
    int node = (blockIdx.x * blockDim.x + threadIdx.x) >> 5;
    if (node >= NN) return;
    int lane = threadIdx.x & 31;
    int start = g_rowptr[node], end = g_rowptr[node + 1];
    int h = lane & 7, eo = lane >> 3;
    float xd  = g_xd[node * 8 + h];
    float avp = g_avp[h], avn = g_avn[h];
    float e0 = g_ete[h], e1 = g_ete[8 + h], e2 = g_ete[16 + h];
    // pass A: running max over logits (4 edges x 8 heads per iteration)
    float mx = -INFINITY;
    for (int base = start; base < end; base += 4) {
        int pos = base + eo;
        float l = -INFINITY;
        if (pos < end) {
            int s = g_srcs[pos];
            float a = g_eas[pos];
            int lt = g_lts[pos];
            float et = (lt == 0) ? e0 : ((lt == 1) ? e1 : e2);
            float v = xd + g_xs[s * 8 + h] + et + a * (a > 0.f ? avp : avn);
            l = v > 0.f ? v : 0.2f * v;
        }
        mx = fmaxf(mx, l);
    }
    mx = fmaxf(mx, __shfl_xor_sync(0xffffffffu, mx, 8));
    mx = fmaxf(mx, __shfl_xor_sync(0xffffffffu, mx, 16));
    // pass B: exp + sum + weighted aggregation; lane = channel, serial edges
    float cvp = g_cvp[lane], cvn = g_cvn[lane];
    float ssum = 0.f;
    float acc[8] = {0.f, 0.f, 0.f, 0.f, 0.f, 0.f, 0.f, 0.f};
    for (int pos = start; pos < end; pos++) {
        int s = g_srcs[pos];
        float a = g_eas[pos];
        int lt = g_lts[pos];
        float et = (lt == 0) ? e0 : ((lt == 1) ? e1 : e2);
        float v = xd + g_xs[s * 8 + h] + et + a * (a > 0.f ? avp : avn);
        v = v > 0.f ? v : 0.2f * v;
        float ev = expf(v - mx);
        ssum += ev;
        float msg = g_xlin[s * 32 + lane] + a * (a > 0.f ? cvp : cvn);
        #pragma unroll
        for (int hh = 0; hh < 8; hh++) {
            float aw = __shfl_sync(0xffffffffu, ev, hh);
            acc[hh] = fmaf(aw, msg, acc[hh]);
        }
    }
    float inv = 1.f / (ssum + 1e-16f);
    // fused epilogue: v[hh] = hconv + residual; LayerNorm over the 256 row
    float vrow[8];
    #pragma unroll
    for (int hh = 0; hh < 8; hh++) {
        float ih = __shfl_sync(0xffffffffu, inv, hh);
        vrow[hh] = acc[hh] * ih + g_m[(size_t)node * DD + hh * 32 + lane];
    }
    float s = 0.f, sq = 0.f;
    #pragma unroll
    for (int i = 0; i < 8; i++) { s += vrow[i]; sq += vrow[i] * vrow[i]; }
    #pragma unroll
    for (int o = 16; o > 0; o >>= 1) {
        s  += __shfl_xor_sync(0xffffffffu, s, o);
        sq += __shfl_xor_sync(0xffffffffu, sq, o);
    }
    float mu = s * (1.0f / DD);
    float var = sq * (1.0f / DD) - mu * mu;
    float rs = rsqrtf(var + 1e-5f);
    #pragma unroll
    for (int hh = 0; hh < 8; hh++) {
        int c = hh * 32 + lane;
        g_m[(size_t)node * DD + c] = (vrow[hh] - mu) * rs * gg[c] + bb[c];
    }
}

// -------------- LayerNorm(f + mio) -> mio (warp per row; post-FFN LN2) ---------
__global__ void ln_kernel(const float* __restrict__ f, float* __restrict__ mio,
                          const float* __restrict__ gg, const float* __restrict__ bb) {
    int row = (blockIdx.x * blockDim.x + threadIdx.x) >> 5;
    if (row >= NN) return;
    int lane = threadIdx.x & 31;
    const float4* f4 = (const float4*)(f + (size_t)row * DD);
    const float4* r4 = (const float4*)(mio + (size_t)row * DD);
    float4 a0 = f4[lane * 2], a1 = f4[lane * 2 + 1];
    float4 c0 = r4[lane * 2], c1 = r4[lane * 2 + 1];
    float v[8] = {a0.x + c0.x, a0.y + c0.y, a0.z + c0.z, a0.w + c0.w,
                  a1.x + c1.x, a1.y + c1.y, a1.z + c1.z, a1.w + c1.w};
    float s = 0.f, sq = 0.f;
    #pragma unroll
    for (int i = 0; i < 8; i++) { s += v[i]; sq += v[i] * v[i]; }
    #pragma unroll
    for (int o = 16; o > 0; o >>= 1) {
        s  += __shfl_xor_sync(0xffffffffu, s, o);
        sq += __shfl_xor_sync(0xffffffffu, sq, o);
    }
    float mu = s * (1.0f / DD);
    float var = sq * (1.0f / DD) - mu * mu;
    float rs = rsqrtf(var + 1e-5f);
    int c = lane * 8;
    float o_[8];
    #pragma unroll
    for (int i = 0; i < 8; i++) o_[i] = (v[i] - mu) * rs * gg[c + i] + bb[c + i];
    float4* w4 = (float4*)(mio + (size_t)row * DD);
    w4[lane * 2]     = make_float4(o_[0], o_[1], o_[2], o_[3]);
    w4[lane * 2 + 1] = make_float4(o_[4], o_[5], o_[6], o_[7]);
}

// ---------------- tf32 split-GEMM (3xTF32 accuracy trick) ----------------------
// C[M,N] = A[M,K] @ B[K,N] + bias (optional relu). fp32-equivalent accuracy:
// a = hi + lo (tf32 each); D += Ahi*Bhi + Ahi*Blo + Alo*Bhi; dropped alo*blo
// term is <= 2^-22 relative. Block 128x128xBK16, 8 warps, warp tile 64x32,
// mma.sync.m16n8k8 tf32. B comes pre-split (hi/lo) from split_w_kernel.
// Register-prefetch double buffering: next tile's LDGs issue before compute.
__device__ __forceinline__ void mma_tf32(float* d, const uint32_t* a, const uint32_t* b) {
    asm volatile(
        "mma.sync.aligned.m16n8k8.row.col.f32.tf32.tf32.f32 "
        "{%0,%1,%2,%3}, {%4,%5,%6,%7}, {%8,%9}, {%0,%1,%2,%3};\n"
        : "+f"(d[0]), "+f"(d[1]), "+f"(d[2]), "+f"(d[3])
        : "r"(a[0]), "r"(a[1]), "r"(a[2]), "r"(a[3]), "r"(b[0]), "r"(b[1]));
}

#define GBK 16
__global__ void __launch_bounds__(256)
tf32_gemm_kernel(int M, int Nn, int K,
                 const float* __restrict__ A,
                 const float* __restrict__ Bhp, const float* __restrict__ Blp,
                 const float* __restrict__ bias, float* __restrict__ C, int relu) {
    __shared__ float Ah[GBK][132], Al[GBK][132];  // [k][m]
    __shared__ float Bh[GBK][132], Bl[GBK][132];  // [k][n]
    int tid = threadIdx.x;
    int lane = tid & 31, wid = tid >> 5;
    int wm = wid >> 2, wn = wid & 3;     // warps: 2 (m) x 4 (n)
    int g = lane >> 2, t = lane & 3;     // groupID, threadID_in_group
    int row0 = blockIdx.y * 128, col0 = blockIdx.x * 128;

    // per-thread tile-fill coordinates (fixed across iterations)
    int ar0 = (tid * 2)     >> 2, ak0 = ((tid * 2)     & 3) * 4;  // A frag 0
    int ar1 = (tid * 2 + 1) >> 2, ak1 = ((tid * 2 + 1) & 3) * 4;  // A frag 1
    int bk0 = tid >> 5,          bn0 = (tid & 31) * 4;            // B frag 0
    int bk1 = (tid + 256) >> 5,  bn1 = bn0;                       // B frag 1

    float acc[4][4][4];
    #pragma unroll
    for (int i = 0; i < 4; i++)
        #pragma unroll
        for (int j = 0; j < 4; j++)
            #pragma unroll
            for (int r = 0; r < 4; r++) acc[i][j][r] = 0.f;

    float4 aP0, aP1, bhP0, bhP1, blP0, blP1;

    // ---- load tile k0=0 into registers ----
    {
        aP0 = (row0 + ar0 < M) ? *(const float4*)(A + (size_t)(row0 + ar0) * K + ak0)
                               : make_float4(0.f, 0.f, 0.f, 0.f);
        aP1 = (row0 + ar1 < M) ? *(const float4*)(A + (size_t)(row0 + ar1) * K + ak1)
                               : make_float4(0.f, 0.f, 0.f, 0.f);
        size_t o0 = (size_t)bk0 * Nn + col0 + bn0;
        size_t o1 = (size_t)bk1 * Nn + col0 + bn1;
        bhP0 = *(const float4*)(Bhp + o0); blP0 = *(const float4*)(Blp + o0);
        bhP1 = *(const float4*)(Bhp + o1); blP1 = *(const float4*)(Blp + o1);
    }
    // ---- store tile 0 to smem ----
    {
        float hi, lo;
        tf32_split(aP0.x, hi, lo); Ah[ak0 + 0][ar0] = hi; Al[ak0 + 0][ar0] = lo;
        tf32_split(aP0.y, hi, lo); Ah[ak0 + 1][ar0] = hi; Al[ak0 + 1][ar0] = lo;
        tf32_split(aP0.z, hi, lo); Ah[ak0 + 2][ar0] = hi; Al[ak0 + 2][ar0] = lo;
        tf32_split(aP0.w, hi, lo); Ah[ak0 + 3][ar0] = hi; Al[ak0 + 3][ar0] = lo;
        tf32_split(aP1.x, hi, lo); Ah[ak1 + 0][ar1] = hi; Al[ak1 + 0][ar1] = lo;
        tf32_split(aP1.y, hi, lo); Ah[ak1 + 1][ar1] = hi; Al[ak1 + 1][ar1] = lo;
        tf32_split(aP1.z, hi, lo); Ah[ak1 + 2][ar1] = hi; Al[ak1 + 2][ar1] = lo;
        tf32_split(aP1.w, hi, lo); Ah[ak1 + 3][ar1] = hi; Al[ak1 + 3][ar1] = lo;
        *(float4*)(&Bh[bk0][bn0]) = bhP0; *(float4*)(&Bl[bk0][bn0]) = blP0;
        *(float4*)(&Bh[bk1][bn1]) = bhP1; *(float4*)(&Bl[bk1][bn1]) = blP1;
    }
    __syncthreads();

    for (int k0 = 0; k0 < K; k0 += GBK) {
        // ---- prefetch next tile into registers (overlaps with compute below) ----
        bool more = (k0 + GBK) < K;
        if (more) {
            int kn = k0 + GBK;
            aP0 = (row0 + ar0 < M) ? *(const float4*)(A + (size_t)(row0 + ar0) * K + kn + ak0)
                                   : make_float4(0.f, 0.f, 0.f, 0.f);
            aP1 = (row0 + ar1 < M) ? *(const float4*)(A + (size_t)(row0 + ar1) * K + kn + ak1)
                                   : make_float4(0.f, 0.f, 0.f, 0.f);
            size_t o0 = (size_t)(kn + bk0) * Nn + col0 + bn0;
            size_t o1 = (size_t)(kn + bk1) * Nn + col0 + bn1;
            bhP0 = *(const float4*)(Bhp + o0); blP0 = *(const float4*)(Blp + o0);
            bhP1 = *(const float4*)(Bhp + o1); blP1 = *(const float4*)(Blp + o1);
        }

        // ---- compute on current smem tile ----
        #pragma unroll
        for (int ks = 0; ks < GBK; ks += 8) {
            uint32_t bhf[4][2], blf[4][2];
            #pragma unroll
            for (int nj = 0; nj < 4; nj++) {
                int n = wn * 32 + nj * 8 + g;
                bhf[nj][0] = __float_as_uint(Bh[ks + t][n]);
                bhf[nj][1] = __float_as_uint(Bh[ks + t + 4][n]);
                blf[nj][0] = __float_as_uint(Bl[ks + t][n]);
                blf[nj][1] = __float_as_uint(Bl[ks + t + 4][n]);
            }
            #pragma unroll
            for (int mi = 0; mi < 4; mi++) {
                int m = wm * 64 + mi * 16;
                uint32_t ahf[4], alf[4];
                ahf[0] = __float_as_uint(Ah[ks + t][m + g]);
                ahf[1] = __float_as_uint(Ah[ks + t][m + g + 8]);
                ahf[2] = __float_as_uint(Ah[ks + t + 4][m + g]);
                ahf[3] = __float_as_uint(Ah[ks + t + 4][m + g + 8]);
                alf[0] = __float_as_uint(Al[ks + t][m + g]);
                alf[1] = __float_as_uint(Al[ks + t][m + g + 8]);
                alf[2] = __float_as_uint(Al[ks + t + 4][m + g]);
                alf[3] = __float_as_uint(Al[ks + t + 4][m + g + 8]);
                #pragma unroll
                for (int nj = 0; nj < 4; nj++) {
                    mma_tf32(acc[mi][nj], ahf, bhf[nj]);   // hi*hi
                    mma_tf32(acc[mi][nj], ahf, blf[nj]);   // hi*lo
                    mma_tf32(acc[mi][nj], alf, bhf[nj]);   // lo*hi
                }
            }
        }
        __syncthreads();

        // ---- store prefetched tile to smem ----
        if (more) {
            float hi, lo;
            tf32_split(aP0.x, hi, lo); Ah[ak0 + 0][ar0] = hi; Al[ak0 + 0][ar0] = lo;
            tf32_split(aP0.y, hi, lo); Ah[ak0 + 1][ar0] = hi; Al[ak0 + 1][ar0] = lo;
            tf32_split(aP0.z, hi, lo); Ah[ak0 + 2][ar0] = hi; Al[ak0 + 2][ar0] = lo;
            tf32_split(aP0.w, hi, lo); Ah[ak0 + 3][ar0] = hi; Al[ak0 + 3][ar0] = lo;
            tf32_split(aP1.x, hi, lo); Ah[ak1 + 0][ar1] = hi; Al[ak1 + 0][ar1] = lo;
            tf32_split(aP1.y, hi, lo); Ah[ak1 + 1][ar1] = hi; Al[ak1 + 1][ar1] = lo;
            tf32_split(aP1.z, hi, lo); Ah[ak1 + 2][ar1] = hi; Al[ak1 + 2][ar1] = lo;
            tf32_split(aP1.w, hi, lo); Ah[ak1 + 3][ar1] = hi; Al[ak1 + 3][ar1] = lo;
            *(float4*)(&Bh[bk0][bn0]) = bhP0; *(float4*)(&Bl[bk0][bn0]) = blP0;
            *(float4*)(&Bh[bk1][bn1]) = bhP1; *(float4*)(&Bl[bk1][bn1]) = blP1;
            __syncthreads();
        }
    }

    // epilogue: c0 (row g, col 2t), c1 (row g, 2t+1), c2 (row g+8, 2t), c3 (g+8, 2t+1)
    #pragma unroll
    for (int nj = 0; nj < 4; nj++) {
        int cb = col0 + wn * 32 + nj * 8 + 2 * t;
        float b0 = bias[cb], b1 = bias[cb + 1];
        #pragma unroll
        for (int mi = 0; mi < 4; mi++) {
            int r0 = row0 + wm * 64 + mi * 16 + g;
            float v0 = acc[mi][nj][0] + b0;
            float v1 = acc[mi][nj][1] + b1;
            float v2 = acc[mi][nj][2] + b0;
            float v3 = acc[mi][nj][3] + b1;
            if (relu) {
                v0 = fmaxf(v0, 0.f); v1 = fmaxf(v1, 0.f);
                v2 = fmaxf(v2, 0.f); v3 = fmaxf(v3, 0.f);
            }
            if (r0 < M) {
                C[(size_t)r0 * Nn + cb]     = v0;
                C[(size_t)r0 * Nn + cb + 1] = v1;
            }
            if (r0 + 8 < M) {
                C[(size_t)(r0 + 8) * Nn + cb]     = v2;
                C[(size_t)(r0 + 8) * Nn + cb + 1] = v3;
            }
        }
    }
}

// -------------------------------- launcher -------------------------------------
extern "C" void kernel_launch(void* const* d_in, const int* in_sizes, int n_in,
                              void* d_out, int out_size) {
    const float* x     = (const float*)d_in[0];
    const int*   ei    = (const int*)  d_in[1];
    const float* ea    = (const float*)d_in[2];
    const int*   ntype = (const int*)  d_in[3];
    const int*   ltype = (const int*)  d_in[4];
    const float* Wh    = (const float*)d_in[5];
    const float* bh    = (const float*)d_in[6];
    const float* Et    = (const float*)d_in[7];
    const float* Wea   = (const float*)d_in[8];
    const float* Watt  = (const float*)d_in[9];
    const float* Wlin  = (const float*)d_in[10];
    const float* w1    = (const float*)d_in[11];
    const float* b1    = (const float*)d_in[12];
    const float* w2    = (const float*)d_in[13];
    const float* b2    = (const float*)d_in[14];
    const float* ln1g  = (const float*)d_in[15];
    const float* ln1b  = (const float*)d_in[16];
    const float* ln2g  = (const float*)d_in[17];
    const float* ln2b  = (const float*)d_in[18];
    const int* srcp = ei;
    const int* dstp = ei + EE;

    void *pm, *pf, *ph, *pw1h, *pw1l, *pw2h, *pw2l;
    cudaGetSymbolAddress(&pm, g_m);
    cudaGetSymbolAddress(&pf, g_f);
    cudaGetSymbolAddress(&ph, g_hidden);
    cudaGetSymbolAddress(&pw1h, g_w1h);
    cudaGetSymbolAddress(&pw1l, g_w1l);
    cudaGetSymbolAddress(&pw2h, g_w2h);
    cudaGetSymbolAddress(&pw2l, g_w2l);
    float* m_ptr = (float*)pm;
    float* f_ptr = (float*)pf;
    float* h_ptr = (float*)ph;
    const float* w1h = (const float*)pw1h;
    const float* w1l = (const float*)pw1l;
    const float* w2h = (const float*)pw2h;
    const float* w2l = (const float*)pw2l;

    // ---- per-launch preprocessing (step-invariant) ----
    zero_kernel<<<(NN + 255) / 256, 256>>>();
    hist_kernel<<<(EE + 255) / 256, 256>>>(dstp);
    scan_kernel<<<1, 1024>>>();
    scatter_kernel<<<(EE + 255) / 256, 256>>>(srcp, dstp, ea, ltype);
    prep_tables_kernel<<<1, 32>>>(Wea, Watt, Et, Wlin);
    split_w_kernel<<<(STEPS * DD * HID + 255) / 256, 256>>>(w1, w2);
    cudaMemcpyAsync(m_ptr, x, (size_t)NN * DD * sizeof(float),
                    cudaMemcpyDeviceToDevice, 0);

    int hetero_blocks = (((NN + 3) / 4) * 32 + 255) / 256;
    int warpN_blocks  = (NN * 32 + 255) / 256;
    dim3 g1(HID / 128, (NN + 127) / 128);
    dim3 g2(DD / 128, (NN + 127) / 128);

    for (int s = 0; s < STEPS; s++) {
        hetero_kernel<<<hetero_blocks, 256>>>(ntype, Wh, bh, Watt, Wlin);
        att_ln_kernel<<<warpN_blocks, 256>>>(ln1g + s * DD, ln1b + s * DD);
        tf32_gemm_kernel<<<g1, 256>>>(NN, HID, DD, m_ptr,
                                      w1h + (size_t)s * DD * HID, w1l + (size_t)s * DD * HID,
                                      b1 + (size_t)s * HID, h_ptr, 1);
        tf32_gemm_kernel<<<g2, 256>>>(NN, DD, HID, h_ptr,
                                      w2h + (size_t)s * HID * DD, w2l + (size_t)s * HID * DD,
                                      b2 + (size_t)s * DD, f_ptr, 0);
        ln_kernel<<<warpN_blocks, 256>>>(f_ptr, m_ptr, ln2g + s * DD, ln2b + s * DD);
    }
    cudaMemcpyAsync(d_out, m_ptr, (size_t)NN * DD * sizeof(float),
                    cudaMemcpyDeviceToDevice, 0);
}

// round 9
// speedup vs baseline: 1.6770x; 1.6770x over previous
#include <cuda_runtime.h>
#include <cuda_bf16.h>
#include <math.h>
#include <stdint.h>

#define NN 50000
#define EE 800000
#define DD 256
#define HID 1024
#define STEPS 6

// ---------------- scratch (device globals; no runtime allocation) -------------
__device__ int   g_deg[NN];
__device__ int   g_tmp[NN];
__device__ int   g_rowptr[NN + 1];
__device__ int   g_srcs[EE];
__device__ float g_eas[EE];           // edge_attr, CSR-sorted
__device__ int   g_lts[EE];           // link_type, CSR-sorted
__device__ float g_xd[NN * 8];        // x @ Watt[0:32]
__device__ float g_xs[NN * 8];        // x @ Watt[32:64]
__device__ float g_xlin[NN * 32];     // x @ Wlin[0:32]
__device__ float g_m[NN * DD];        // running node state
__device__ float g_f[NN * DD];        // FFN out scratch
__device__ float g_hidden[NN * HID];  // FFN hidden
// rank-1 edge-constant tables (leaky is positively homogeneous in scalar ea)
__device__ float g_cvp[32], g_cvn[32];   // message vec for a>0 / a<0
__device__ float g_avp[8],  g_avn[8];    // attention vec for a>0 / a<0
__device__ float g_ete[3 * 8];           // link-type attention table
// pre-split FFN weights: bf16 hi/lo, TRANSPOSED [n][k/2] pair-packed layout
__device__ uint32_t g_w1h[STEPS * HID * (DD / 2)];
__device__ uint32_t g_w1l[STEPS * HID * (DD / 2)];
__device__ uint32_t g_w2h[STEPS * DD * (HID / 2)];
__device__ uint32_t g_w2l[STEPS * DD * (HID / 2)];

// ---------------- bf16 split helpers -------------------------------------------
__device__ __forceinline__ float bf16_hi(float x) {
    return __bfloat162float(__float2bfloat16(x));
}
__device__ __forceinline__ uint32_t pack2(float lo_elem, float hi_elem) {
    __nv_bfloat162 p = __floats2bfloat162_rn(lo_elem, hi_elem);  // .x = low 16 bits
    return *reinterpret_cast<uint32_t*>(&p);
}

// ---------------- preprocessing ------------------------------------------------
__global__ void zero_kernel() {
    int i = blockIdx.x * blockDim.x + threadIdx.x;
    if (i < NN) { g_deg[i] = 0; g_tmp[i] = 0; }
}

__global__ void hist_kernel(const int* __restrict__ dst) {
    int e = blockIdx.x * blockDim.x + threadIdx.x;
    if (e < EE) atomicAdd(&g_deg[dst[e]], 1);
}

__global__ void scan_kernel() {
    __shared__ int ws[32];
    __shared__ int carry_s;
    int tid = threadIdx.x, lane = tid & 31, wid = tid >> 5;
    if (tid == 0) carry_s = 0;
    __syncthreads();
    for (int base = 0; base < NN; base += 1024) {
        int i = base + tid;
        int v = (i < NN) ? g_deg[i] : 0;
        int x = v;
        #pragma unroll
        for (int o = 1; o < 32; o <<= 1) {
            int y = __shfl_up_sync(0xffffffffu, x, o);
            if (lane >= o) x += y;
        }
        if (lane == 31) ws[wid] = x;
        __syncthreads();
        if (tid < 32) {
            int w = ws[tid];
            #pragma unroll
            for (int o = 1; o < 32; o <<= 1) {
                int y = __shfl_up_sync(0xffffffffu, w, o);
                if (tid >= o) w += y;
            }
            ws[tid] = w;
        }
        __syncthreads();
        int incl = x + (wid > 0 ? ws[wid - 1] : 0);
        int carry = carry_s;
        if (i < NN) g_rowptr[i] = carry + incl - v;  // exclusive
        __syncthreads();
        if (tid == 1023) carry_s = carry + incl;
        __syncthreads();
    }
    if (tid == 0) g_rowptr[NN] = carry_s;
}

// CSR scatter: also gather per-edge scalars (edge_attr, link_type) directly
__global__ void scatter_kernel(const int* __restrict__ src, const int* __restrict__ dst,
                               const float* __restrict__ ea, const int* __restrict__ ltype) {
    int e = blockIdx.x * blockDim.x + threadIdx.x;
    if (e >= EE) return;
    int d = dst[e];
    int r = atomicAdd(&g_tmp[d], 1);
    int pos = g_rowptr[d] + r;
    g_srcs[pos] = src[e];
    g_eas[pos]  = ea[e];
    g_lts[pos]  = ltype[e];
}

// rank-1 edge-constant tables. leaky(a*w) = a*leaky(w) for a>0,
// = a*leakyneg(w) for a<0, where leakyneg(w) = (w>0 ? 0.2w : w).
__global__ void prep_tables_kernel(const float* __restrict__ Wea,
                                   const float* __restrict__ Watt,
                                   const float* __restrict__ Et,
                                   const float* __restrict__ Wlin) {
    int lane = threadIdx.x;  // one warp
    float cp = 0.f, cn = 0.f;
    #pragma unroll
    for (int j = 0; j < 50; j++) {
        float w = Wea[j];
        float lp = w > 0.f ? w : 0.2f * w;        // leaky(w)
        float ln_ = w > 0.f ? 0.2f * w : w;       // leakyneg(w)
        float wl = Wlin[(32 + j) * 32 + lane];
        cp = fmaf(lp, wl, cp);
        cn = fmaf(ln_, wl, cn);
    }
    g_cvp[lane] = cp; g_cvn[lane] = cn;
    if (lane < 8) {
        float ap = 0.f, an = 0.f;
        #pragma unroll
        for (int j = 0; j < 50; j++) {
            float w = Wea[j];
            float lp = w > 0.f ? w : 0.2f * w;
            float ln_ = w > 0.f ? 0.2f * w : w;
            float wa = Watt[(74 + j) * 8 + lane];
            ap = fmaf(lp, wa, ap);
            an = fmaf(ln_, wa, an);
        }
        g_avp[lane] = ap; g_avn[lane] = an;
        #pragma unroll
        for (int lt = 0; lt < 3; lt++) {
            float s = 0.f;
            #pragma unroll
            for (int j = 0; j < 10; j++) {
                float t = Et[lt * 10 + j];
                t = t > 0.f ? t : 0.2f * t;
                s = fmaf(t, Watt[(64 + j) * 8 + lane], s);
            }
            g_ete[lt * 8 + lane] = s;
        }
    }
}

// split both FFN weight tensors into bf16 hi/lo, transposed [n][k/2]-pair layout.
// w1 logical: [s][k(DD)][n(HID)]  -> g_w1h/l [s][n][kp]  (kp = k/2)
// w2 logical: [s][k(HID)][n(DD)] -> g_w2h/l [s][n][kp]
__global__ void split_w_kernel(const float* __restrict__ w1, const float* __restrict__ w2) {
    int i = blockIdx.x * blockDim.x + threadIdx.x;
    const int n1 = STEPS * HID * (DD / 2);   // == STEPS * DD * (HID / 2)
    if (i >= n1) return;
    {
        int s = i / (HID * (DD / 2));
        int rem = i % (HID * (DD / 2));
        int n = rem / (DD / 2);
        int kp = rem % (DD / 2);
        const float* base = w1 + (size_t)s * DD * HID;
        float b0 = base[(size_t)(2 * kp) * HID + n];
        float b1 = base[(size_t)(2 * kp + 1) * HID + n];
        float h0 = bf16_hi(b0), h1 = bf16_hi(b1);
        g_w1h[i] = pack2(h0, h1);
        g_w1l[i] = pack2(b0 - h0, b1 - h1);
    }
    {
        int s = i / (DD * (HID / 2));
        int rem = i % (DD * (HID / 2));
        int n = rem / (HID / 2);
        int kp = rem % (HID / 2);
        const float* base = w2 + (size_t)s * HID * DD;
        float b0 = base[(size_t)(2 * kp) * DD + n];
        float b1 = base[(size_t)(2 * kp + 1) * DD + n];
        float h0 = bf16_hi(b0), h1 = bf16_hi(b1);
        g_w2h[i] = pack2(h0, h1);
        g_w2l[i] = pack2(b0 - h0, b1 - h1);
    }
}

// -------------- per-step: HeteroLinear + fused projections ---------------------
__global__ void hetero_kernel(const int* __restrict__ ntype,
                              const float* __restrict__ Wh, const float* __restrict__ bh,
                              const float* __restrict__ Watt, const float* __restrict__ Wlin) {
    int warp = (blockIdx.x * blockDim.x + threadIdx.x) >> 5;
    int lane = threadIdx.x & 31;
    int n0 = warp * 4;
    if (n0 >= NN) return;
    float acc0[4] = {0.f, 0.f, 0.f, 0.f};
    float acc1[4] = {0.f, 0.f, 0.f, 0.f};
    for (int j = 0; j < DD; j += 4) {
        float mv[4][4];
        #pragma unroll
        for (int q = 0; q < 4; q++) {
            int n = n0 + q;
            float4 t = (n < NN) ? *(const float4*)(g_m + (size_t)n * DD + j)
                                : make_float4(0.f, 0.f, 0.f, 0.f);
            mv[q][0] = t.x; mv[q][1] = t.y; mv[q][2] = t.z; mv[q][3] = t.w;
        }
        #pragma unroll
        for (int jj = 0; jj < 4; jj++) {
            float w0 = Wh[(j + jj) * 32 + lane];
            float w1 = Wh[DD * 32 + (j + jj) * 32 + lane];
            #pragma unroll
            for (int q = 0; q < 4; q++) {
                acc0[q] = fmaf(mv[q][jj], w0, acc0[q]);
                acc1[q] = fmaf(mv[q][jj], w1, acc1[q]);
            }
        }
    }
    for (int q = 0; q < 4; q++) {
        int n = n0 + q;
        if (n >= NN) break;
        int t = ntype[n];
        float xv = (t == 0 ? acc0[q] : acc1[q]) + bh[t * 32 + lane];
        #pragma unroll
        for (int h = 0; h < 8; h++) {
            float pd = xv * Watt[lane * 8 + h];
            float ps = xv * Watt[(32 + lane) * 8 + h];
            #pragma unroll
            for (int o = 16; o > 0; o >>= 1) {
                pd += __shfl_xor_sync(0xffffffffu, pd, o);
                ps += __shfl_xor_sync(0xffffffffu, ps, o);
            }
            if (lane == 0) { g_xd[n * 8 + h] = pd; g_xs[n * 8 + h] = ps; }
        }
        float xl = 0.f;
        #pragma unroll
        for (int c = 0; c < 32; c++) {
            float xb = __shfl_sync(0xffffffffu, xv, c);
            xl = fmaf(xb, Wlin[c * 32 + lane], xl);
        }
        g_xlin[n * 32 + lane] = xl;
    }
}

// -------------- per-step: attention + aggregation + fused LayerNorm-1 ----------
__global__ void att_ln_kernel(const float* __restrict__ gg, const float* __restrict__ bb) {
    int node = (blockIdx.x * blockDim.x + threadIdx.x) >> 5;
    if (node >= NN) return;
    int lane = threadIdx.x & 31;
    int start = g_rowptr[node], end = g_rowptr[node + 1];
    int h = lane & 7, eo = lane >> 3;
    float xd  = g_xd[node * 8 + h];
    float avp = g_avp[h], avn = g_avn[h];
    float e0 = g_ete[h], e1 = g_ete[8 + h], e2 = g_ete[16 + h];
    float mx = -INFINITY;
    for (int base = start; base < end; base += 4) {
        int pos = base + eo;
        float l = -INFINITY;
        if (pos < end) {
            int s = g_srcs[pos];
            float a = g_eas[pos];
            int lt = g_lts[pos];
            float et = (lt == 0) ? e0 : ((lt == 1) ? e1 : e2);
            float v = xd + g_xs[s * 8 + h] + et + a * (a > 0.f ? avp : avn);
            l = v > 0.f ? v : 0.2f * v;
        }
        mx = fmaxf(mx, l);
    }
    mx = fmaxf(mx, __shfl_xor_sync(0xffffffffu, mx, 8));
    mx = fmaxf(mx, __shfl_xor_sync(0xffffffffu, mx, 16));
    float cvp = g_cvp[lane], cvn = g_cvn[lane];
    float ssum = 0.f;
    float acc[8] = {0.f, 0.f, 0.f, 0.f, 0.f, 0.f, 0.f, 0.f};
    for (int pos = start; pos < end; pos++) {
        int s = g_srcs[pos];
        float a = g_eas[pos];
        int lt = g_lts[pos];
        float et = (lt == 0) ? e0 : ((lt == 1) ? e1 : e2);
        float v = xd + g_xs[s * 8 + h] + et + a * (a > 0.f ? avp : avn);
        v = v > 0.f ? v : 0.2f * v;
        float ev = expf(v - mx);
        ssum += ev;
        float msg = g_xlin[s * 32 + lane] + a * (a > 0.f ? cvp : cvn);
        #pragma unroll
        for (int hh = 0; hh < 8; hh++) {
            float aw = __shfl_sync(0xffffffffu, ev, hh);
            acc[hh] = fmaf(aw, msg, acc[hh]);
        }
    }
    float inv = 1.f / (ssum + 1e-16f);
    float vrow[8];
    #pragma unroll
    for (int hh = 0; hh < 8; hh++) {
        float ih = __shfl_sync(0xffffffffu, inv, hh);
        vrow[hh] = acc[hh] * ih + g_m[(size_t)node * DD + hh * 32 + lane];
    }
    float s = 0.f, sq = 0.f;
    #pragma unroll
    for (int i = 0; i < 8; i++) { s += vrow[i]; sq += vrow[i] * vrow[i]; }
    #pragma unroll
    for (int o = 16; o > 0; o >>= 1) {
        s  += __shfl_xor_sync(0xffffffffu, s, o);
        sq += __shfl_xor_sync(0xffffffffu, sq, o);
    }
    float mu = s * (1.0f / DD);
    float var = sq * (1.0f / DD) - mu * mu;
    float rs = rsqrtf(var + 1e-5f);
    #pragma unroll
    for (int hh = 0; hh < 8; hh++) {
        int c = hh * 32 + lane;
        g_m[(size_t)node * DD + c] = (vrow[hh] - mu) * rs * gg[c] + bb[c];
    }
}

// -------------- LayerNorm(f + mio) -> mio (warp per row; post-FFN LN2) ---------
__global__ void ln_kernel(const float* __restrict__ f, float* __restrict__ mio,
                          const float* __restrict__ gg, const float* __restrict__ bb) {
    int row = (blockIdx.x * blockDim.x + threadIdx.x) >> 5;
    if (row >= NN) return;
    int lane = threadIdx.x & 31;
    const float4* f4 = (const float4*)(f + (size_t)row * DD);
    const float4* r4 = (const float4*)(mio + (size_t)row * DD);
    float4 a0 = f4[lane * 2], a1 = f4[lane * 2 + 1];
    float4 c0 = r4[lane * 2], c1 = r4[lane * 2 + 1];
    float v[8] = {a0.x + c0.x, a0.y + c0.y, a0.z + c0.z, a0.w + c0.w,
                  a1.x + c1.x, a1.y + c1.y, a1.z + c1.z, a1.w + c1.w};
    float s = 0.f, sq = 0.f;
    #pragma unroll
    for (int i = 0; i < 8; i++) { s += v[i]; sq += v[i] * v[i]; }
    #pragma unroll
    for (int o = 16; o > 0; o >>= 1) {
        s  += __shfl_xor_sync(0xffffffffu, s, o);
        sq += __shfl_xor_sync(0xffffffffu, sq, o);
    }
    float mu = s * (1.0f / DD);
    float var = sq * (1.0f / DD) - mu * mu;
    float rs = rsqrtf(var + 1e-5f);
    int c = lane * 8;
    float o_[8];
    #pragma unroll
    for (int i = 0; i < 8; i++) o_[i] = (v[i] - mu) * rs * gg[c + i] + bb[c + i];
    float4* w4 = (float4*)(mio + (size_t)row * DD);
    w4[lane * 2]     = make_float4(o_[0], o_[1], o_[2], o_[3]);
    w4[lane * 2 + 1] = make_float4(o_[4], o_[5], o_[6], o_[7]);
}

// ---------------- bf16x3 split-GEMM (Markidis) ---------------------------------
// C[M,N] = A[M,K] @ B[K,N] + bias (optional relu). a = hi(bf16) + lo(bf16);
// D += Ahi*Bhi + Ahi*Blo + Alo*Bhi; dropped lo*lo ~2^-16 relative.
// Block 128x128xBK32, 256 threads, 8 warps 2x4, warp tile 64x32,
// mma.sync.m16n8k16 bf16. B comes pre-split+packed [n][k/2] from split_w_kernel.
// Register-prefetch double buffering. Smem pair-arrays stride 20 words
// (banks (20g+t)%32 distinct for g in 0..7, t in 0..3 -> conflict-free frags).
__device__ __forceinline__ void mma_bf16(float* d, const uint32_t* a, const uint32_t* b) {
    asm volatile(
        "mma.sync.aligned.m16n8k16.row.col.f32.bf16.bf16.f32 "
        "{%0,%1,%2,%3}, {%4,%5,%6,%7}, {%8,%9}, {%0,%1,%2,%3};\n"
        : "+f"(d[0]), "+f"(d[1]), "+f"(d[2]), "+f"(d[3])
        : "r"(a[0]), "r"(a[1]), "r"(a[2]), "r"(a[3]), "r"(b[0]), "r"(b[1]));
}

#define BKK 32
#define SMS 20   // smem row stride in uint32 (16 used + 4 pad)
__global__ void __launch_bounds__(256)
bf16_gemm_kernel(int M, int Nn, int K,
                 const float* __restrict__ A,
                 const uint32_t* __restrict__ Bhp, const uint32_t* __restrict__ Blp,
                 const float* __restrict__ bias, float* __restrict__ C, int relu) {
    __shared__ uint32_t Ah[128][SMS], Al[128][SMS];  // [m][kpair]
    __shared__ uint32_t Bh[128][SMS], Bl[128][SMS];  // [n][kpair]
    int tid = threadIdx.x;
    int lane = tid & 31, wid = tid >> 5;
    int wm = wid >> 2, wn = wid & 3;     // warps: 2 (m) x 4 (n)
    int g = lane >> 2, t = lane & 3;     // groupID, threadID_in_group
    int row0 = blockIdx.y * 128, col0 = blockIdx.x * 128;
    int Kh = K >> 1;

    float acc[4][4][4];
    #pragma unroll
    for (int i = 0; i < 4; i++)
        #pragma unroll
        for (int j = 0; j < 4; j++)
            #pragma unroll
            for (int r = 0; r < 4; r++) acc[i][j][r] = 0.f;

    float4 aP[4];
    uint4  bhP[2], blP[2];

    // ---- load tile k0=0 into registers ----
    #pragma unroll
    for (int i = 0; i < 4; i++) {
        int f = tid + 256 * i;
        int r = f >> 3, kq = (f & 7) * 4;
        aP[i] = (row0 + r < M) ? *(const float4*)(A + (size_t)(row0 + r) * K + kq)
                               : make_float4(0.f, 0.f, 0.f, 0.f);
    }
    #pragma unroll
    for (int i = 0; i < 2; i++) {
        int q = tid + 256 * i;
        int n = q >> 2, kq = (q & 3) * 4;
        size_t o = (size_t)(col0 + n) * Kh + kq;
        bhP[i] = *(const uint4*)(Bhp + o);
        blP[i] = *(const uint4*)(Blp + o);
    }
    // ---- store tile 0 to smem ----
    #pragma unroll
    for (int i = 0; i < 4; i++) {
        int f = tid + 256 * i;
        int r = f >> 3, kp = (f & 7) * 2;
        float4 v = aP[i];
        float h0 = bf16_hi(v.x), h1 = bf16_hi(v.y), h2 = bf16_hi(v.z), h3 = bf16_hi(v.w);
        Ah[r][kp]     = pack2(h0, h1);
        Ah[r][kp + 1] = pack2(h2, h3);
        Al[r][kp]     = pack2(v.x - h0, v.y - h1);
        Al[r][kp + 1] = pack2(v.z - h2, v.w - h3);
    }
    #pragma unroll
    for (int i = 0; i < 2; i++) {
        int q = tid + 256 * i;
        int n = q >> 2, kq = (q & 3) * 4;
        *(uint4*)(&Bh[n][kq]) = bhP[i];
        *(uint4*)(&Bl[n][kq]) = blP[i];
    }
    __syncthreads();

    for (int k0 = 0; k0 < K; k0 += BKK) {
        bool more = (k0 + BKK) < K;
        // ---- prefetch next tile into registers ----
        if (more) {
            int kn = k0 + BKK;
            #pragma unroll
            for (int i = 0; i < 4; i++) {
                int f = tid + 256 * i;
                int r = f >> 3, kq = (f & 7) * 4;
                aP[i] = (row0 + r < M) ? *(const float4*)(A + (size_t)(row0 + r) * K + kn + kq)
                                       : make_float4(0.f, 0.f, 0.f, 0.f);
            }
            #pragma unroll
            for (int i = 0; i < 2; i++) {
                int q = tid + 256 * i;
                int n = q >> 2, kq = (q & 3) * 4;
                size_t o = (size_t)(col0 + n) * Kh + (kn >> 1) + kq;
                bhP[i] = *(const uint4*)(Bhp + o);
                blP[i] = *(const uint4*)(Blp + o);
            }
        }

        // ---- compute on current smem tile (two K=16 chunks) ----
        #pragma unroll
        for (int ks = 0; ks < BKK; ks += 16) {
            int kp = ks >> 1;  // 0 or 8
            uint32_t bhf[4][2], blf[4][2];
            #pragma unroll
            for (int nj = 0; nj < 4; nj++) {
                int n = wn * 32 + nj * 8 + g;
                bhf[nj][0] = Bh[n][kp + t];
                bhf[nj][1] = Bh[n][kp + t + 4];
                blf[nj][0] = Bl[n][kp + t];
                blf[nj][1] = Bl[n][kp + t + 4];
            }
            #pragma unroll
            for (int mi = 0; mi < 4; mi++) {
                int m = wm * 64 + mi * 16;
                uint32_t ahf[4], alf[4];
                ahf[0] = Ah[m + g][kp + t];
                ahf[1] = Ah[m + g + 8][kp + t];
                ahf[2] = Ah[m + g][kp + t + 4];
                ahf[3] = Ah[m + g + 8][kp + t + 4];
                alf[0] = Al[m + g][kp + t];
                alf[1] = Al[m + g + 8][kp + t];
                alf[2] = Al[m + g][kp + t + 4];
                alf[3] = Al[m + g + 8][kp + t + 4];
                #pragma unroll
                for (int nj = 0; nj < 4; nj++) {
                    mma_bf16(acc[mi][nj], ahf, bhf[nj]);   // hi*hi
                    mma_bf16(acc[mi][nj], ahf, blf[nj]);   // hi*lo
                    mma_bf16(acc[mi][nj], alf, bhf[nj]);   // lo*hi
                }
            }
        }
        __syncthreads();

        // ---- store prefetched tile to smem ----
        if (more) {
            #pragma unroll
            for (int i = 0; i < 4; i++) {
                int f = tid + 256 * i;
                int r = f >> 3, kp = (f & 7) * 2;
                float4 v = aP[i];
                float h0 = bf16_hi(v.x), h1 = bf16_hi(v.y), h2 = bf16_hi(v.z), h3 = bf16_hi(v.w);
                Ah[r][kp]     = pack2(h0, h1);
                Ah[r][kp + 1] = pack2(h2, h3);
                Al[r][kp]     = pack2(v.x - h0, v.y - h1);
                Al[r][kp + 1] = pack2(v.z - h2, v.w - h3);
            }
            #pragma unroll
            for (int i = 0; i < 2; i++) {
                int q = tid + 256 * i;
                int n = q >> 2, kq = (q & 3) * 4;
                *(uint4*)(&Bh[n][kq]) = bhP[i];
                *(uint4*)(&Bl[n][kq]) = blP[i];
            }
            __syncthreads();
        }
    }

    // epilogue: c0 (row g, col 2t), c1 (row g, 2t+1), c2 (row g+8, 2t), c3 (g+8, 2t+1)
    #pragma unroll
    for (int nj = 0; nj < 4; nj++) {
        int cb = col0 + wn * 32 + nj * 8 + 2 * t;
        float b0 = bias[cb], b1 = bias[cb + 1];
        #pragma unroll
        for (int mi = 0; mi < 4; mi++) {
            int r0 = row0 + wm * 64 + mi * 16 + g;
            float v0 = acc[mi][nj][0] + b0;
            float v1 = acc[mi][nj][1] + b1;
            float v2 = acc[mi][nj][2] + b0;
            float v3 = acc[mi][nj][3] + b1;
            if (relu) {
                v0 = fmaxf(v0, 0.f); v1 = fmaxf(v1, 0.f);
                v2 = fmaxf(v2, 0.f); v3 = fmaxf(v3, 0.f);
            }
            if (r0 < M) {
                C[(size_t)r0 * Nn + cb]     = v0;
                C[(size_t)r0 * Nn + cb + 1] = v1;
            }
            if (r0 + 8 < M) {
                C[(size_t)(r0 + 8) * Nn + cb]     = v2;
                C[(size_t)(r0 + 8) * Nn + cb + 1] = v3;
            }
        }
    }
}

// -------------------------------- launcher -------------------------------------
extern "C" void kernel_launch(void* const* d_in, const int* in_sizes, int n_in,
                              void* d_out, int out_size) {
    const float* x     = (const float*)d_in[0];
    const int*   ei    = (const int*)  d_in[1];
    const float* ea    = (const float*)d_in[2];
    const int*   ntype = (const int*)  d_in[3];
    const int*   ltype = (const int*)  d_in[4];
    const float* Wh    = (const float*)d_in[5];
    const float* bh    = (const float*)d_in[6];
    const float* Et    = (const float*)d_in[7];
    const float* Wea   = (const float*)d_in[8];
    const float* Watt  = (const float*)d_in[9];
    const float* Wlin  = (const float*)d_in[10];
    const float* w1    = (const float*)d_in[11];
    const float* b1    = (const float*)d_in[12];
    const float* w2    = (const float*)d_in[13];
    const float* b2    = (const float*)d_in[14];
    const float* ln1g  = (const float*)d_in[15];
    const float* ln1b  = (const float*)d_in[16];
    const float* ln2g  = (const float*)d_in[17];
    const float* ln2b  = (const float*)d_in[18];
    const int* srcp = ei;
    const int* dstp = ei + EE;

    void *pm, *pf, *ph, *pw1h, *pw1l, *pw2h, *pw2l;
    cudaGetSymbolAddress(&pm, g_m);
    cudaGetSymbolAddress(&pf, g_f);
    cudaGetSymbolAddress(&ph, g_hidden);
    cudaGetSymbolAddress(&pw1h, g_w1h);
    cudaGetSymbolAddress(&pw1l, g_w1l);
    cudaGetSymbolAddress(&pw2h, g_w2h);
    cudaGetSymbolAddress(&pw2l, g_w2l);
    float* m_ptr = (float*)pm;
    float* f_ptr = (float*)pf;
    float* h_ptr = (float*)ph;
    const uint32_t* w1h = (const uint32_t*)pw1h;
    const uint32_t* w1l = (const uint32_t*)pw1l;
    const uint32_t* w2h = (const uint32_t*)pw2h;
    const uint32_t* w2l = (const uint32_t*)pw2l;

    // ---- per-launch preprocessing (step-invariant) ----
    zero_kernel<<<(NN + 255) / 256, 256>>>();
    hist_kernel<<<(EE + 255) / 256, 256>>>(dstp);
    scan_kernel<<<1, 1024>>>();
    scatter_kernel<<<(EE + 255) / 256, 256>>>(srcp, dstp, ea, ltype);
    prep_tables_kernel<<<1, 32>>>(Wea, Watt, Et, Wlin);
    split_w_kernel<<<(STEPS * HID * (DD / 2) + 255) / 256, 256>>>(w1, w2);
    cudaMemcpyAsync(m_ptr, x, (size_t)NN * DD * sizeof(float),
                    cudaMemcpyDeviceToDevice, 0);

    int hetero_blocks = (((NN + 3) / 4) * 32 + 255) / 256;
    int warpN_blocks  = (NN * 32 + 255) / 256;
    dim3 g1(HID / 128, (NN + 127) / 128);
    dim3 g2(DD / 128, (NN + 127) / 128);

    for (int s = 0; s < STEPS; s++) {
        hetero_kernel<<<hetero_blocks, 256>>>(ntype, Wh, bh, Watt, Wlin);
        att_ln_kernel<<<warpN_blocks, 256>>>(ln1g + s * DD, ln1b + s * DD);
        bf16_gemm_kernel<<<g1, 256>>>(NN, HID, DD, m_ptr,
                                      w1h + (size_t)s * HID * (DD / 2),
                                      w1l + (size_t)s * HID * (DD / 2),
                                      b1 + (size_t)s * HID, h_ptr, 1);
        bf16_gemm_kernel<<<g2, 256>>>(NN, DD, HID, h_ptr,
                                      w2h + (size_t)s * DD * (HID / 2),
                                      w2l + (size_t)s * DD * (HID / 2),
                                      b2 + (size_t)s * DD, f_ptr, 0);
        ln_kernel<<<warpN_blocks, 256>>>(f_ptr, m_ptr, ln2g + s * DD, ln2b + s * DD);
    }
    cudaMemcpyAsync(d_out, m_ptr, (size_t)NN * DD * sizeof(float),
                    cudaMemcpyDeviceToDevice, 0);
}